// round 2
// baseline (speedup 1.0000x reference)
#include <cuda_runtime.h>
#include <cstddef>

#define NN   50000
#define NE   20000
#define MM   400000
#define LL   800000
#define HIDD 128
#define BBB  32
#define CCC  10

// ---------------- scratch (static device globals; no allocs) ----------------
__device__ float g_x[(size_t)MM * HIDD];
__device__ float g_agg[(size_t)MM * HIDD];
__device__ float g_h[(size_t)MM * HIDD];
__device__ float g_nodex[(size_t)NN * HIDD];
__device__ float g_edgex[(size_t)NE * HIDD];
__device__ float g_pooled[3 * BBB * HIDD];

// ---------------- utility kernels ----------------
__global__ void zero_kernel(float4* __restrict__ p, size_t n4) {
    size_t i = (size_t)blockIdx.x * blockDim.x + threadIdx.x;
    size_t stride = (size_t)gridDim.x * blockDim.x;
    float4 z = make_float4(0.f, 0.f, 0.f, 0.f);
    for (; i < n4; i += stride) p[i] = z;
}

// dst[m] = (relu?) src[idx[m]]   rows x 128, float4 per thread-quad
__global__ void gather_kernel(const float* __restrict__ src, const int* __restrict__ idx,
                              float* __restrict__ dst, int rows, int relu) {
    int gid = blockIdx.x * blockDim.x + threadIdx.x;
    int m = gid >> 5;
    if (m >= rows) return;
    int c = (gid & 31) << 2;
    int s = __ldg(idx + m);
    float4 v = *(const float4*)(src + (size_t)s * HIDD + c);
    if (relu) {
        v.x = fmaxf(v.x, 0.f); v.y = fmaxf(v.y, 0.f);
        v.z = fmaxf(v.z, 0.f); v.w = fmaxf(v.w, 0.f);
    }
    *(float4*)(dst + (size_t)m * HIDD + c) = v;
}

// out[dsti[e]] += x[ srci ? srci[e] : e ]
__global__ void scatter_add_kernel(const float* __restrict__ x, const int* __restrict__ srci,
                                   const int* __restrict__ dsti, float* __restrict__ out, int n) {
    int gid = blockIdx.x * blockDim.x + threadIdx.x;
    int e = gid >> 5;
    if (e >= n) return;
    int c = (gid & 31) << 2;
    int s = srci ? __ldg(srci + e) : e;
    int d = __ldg(dsti + e);
    float4 v = *(const float4*)(x + (size_t)s * HIDD + c);
    float* o = out + (size_t)d * HIDD + c;
    atomicAdd(o + 0, v.x);
    atomicAdd(o + 1, v.y);
    atomicAdd(o + 2, v.z);
    atomicAdd(o + 3, v.w);
}

// ---------------- fused GEMM: C[M,128] = pro(A) @ W[128,128] + epilogue ----------------
// EPI: 0 = +bias ; 1 = relu(+bias) ; 2 = BN(+bias) ; 3 = relu(BN(+bias))
template <bool FUSE, int EPI>
__global__ __launch_bounds__(128) void gemm128(
    const float* __restrict__ A, const float* __restrict__ G, const float* __restrict__ epsp,
    const float* __restrict__ W, const float* __restrict__ bias,
    const float* __restrict__ gamma, const float* __restrict__ beta,
    float* __restrict__ Cmat, int Mrows)
{
    __shared__ float As[16][65];    // transposed A chunk, padded
    __shared__ float Ws[16][HIDD];  // W chunk

    const int t = threadIdx.x;
    const int bm0 = blockIdx.x * 64;
    const int tr = t & 7;    // row group  (rows tr*8 .. tr*8+7)
    const int tc = t >> 3;   // col group  (cols tc*8 .. tc*8+7)

    float e1 = 1.0f;
    if (FUSE) e1 = 1.0f + __ldg(epsp);

    float acc[8][8];
#pragma unroll
    for (int i = 0; i < 8; i++)
#pragma unroll
        for (int j = 0; j < 8; j++) acc[i][j] = 0.f;

    for (int kb = 0; kb < 8; kb++) {
        // load A chunk [64 x 16] (transposed into smem), fused prologue
#pragma unroll
        for (int j = 0; j < 2; j++) {
            int t4 = t * 2 + j;          // 0..255
            int row = t4 >> 2;           // 0..63
            int cg = t4 & 3;             // 0..3 (group of 4 cols)
            int gr = bm0 + row;
            float4 v = make_float4(0.f, 0.f, 0.f, 0.f);
            if (gr < Mrows) {
                size_t off = (size_t)gr * HIDD + kb * 16 + cg * 4;
                v = *(const float4*)(A + off);
                if (FUSE) {
                    float4 g = *(const float4*)(G + off);
                    v.x = fmaf(e1, v.x, g.x);
                    v.y = fmaf(e1, v.y, g.y);
                    v.z = fmaf(e1, v.z, g.z);
                    v.w = fmaf(e1, v.w, g.w);
                }
            }
            As[cg * 4 + 0][row] = v.x;
            As[cg * 4 + 1][row] = v.y;
            As[cg * 4 + 2][row] = v.z;
            As[cg * 4 + 3][row] = v.w;
        }
        // load W chunk [16 x 128]
#pragma unroll
        for (int j = 0; j < 4; j++) {
            int t4 = t + j * 128;        // 0..511
            int row = t4 >> 5;           // 0..15
            int c4 = t4 & 31;            // 0..31
            *(float4*)(&Ws[row][c4 * 4]) =
                *(const float4*)(W + (size_t)(kb * 16 + row) * HIDD + c4 * 4);
        }
        __syncthreads();

#pragma unroll
        for (int k = 0; k < 16; k++) {
            float a[8], w[8];
#pragma unroll
            for (int i = 0; i < 8; i++) a[i] = As[k][tr * 8 + i];
#pragma unroll
            for (int j = 0; j < 8; j++) w[j] = Ws[k][tc * 8 + j];
#pragma unroll
            for (int i = 0; i < 8; i++)
#pragma unroll
                for (int j = 0; j < 8; j++) acc[i][j] = fmaf(a[i], w[j], acc[i][j]);
        }
        __syncthreads();
    }

    // epilogue
    const float inv_std = rsqrtf(1.0f + 1e-5f);
    float bcol[8], gcol[8], btcol[8];
#pragma unroll
    for (int j = 0; j < 8; j++) {
        int c = tc * 8 + j;
        bcol[j] = __ldg(bias + c);
        if (EPI >= 2) { gcol[j] = __ldg(gamma + c); btcol[j] = __ldg(beta + c); }
    }
#pragma unroll
    for (int i = 0; i < 8; i++) {
        int gr = bm0 + tr * 8 + i;
        if (gr >= Mrows) continue;
        float vals[8];
#pragma unroll
        for (int j = 0; j < 8; j++) {
            float v = acc[i][j] + bcol[j];
            if (EPI == 1) v = fmaxf(v, 0.f);
            if (EPI >= 2) {
                v = gcol[j] * v * inv_std + btcol[j];
                if (EPI == 3) v = fmaxf(v, 0.f);
            }
            vals[j] = v;
        }
        float* o = Cmat + (size_t)gr * HIDD + tc * 8;
        *(float4*)(o + 0) = make_float4(vals[0], vals[1], vals[2], vals[3]);
        *(float4*)(o + 4) = make_float4(vals[4], vals[5], vals[6], vals[7]);
    }
}

// ---------------- per-graph pooling: pooled[b,c] += (relu?) x[nidx[m], c] for batch[m]==b ----
__global__ __launch_bounds__(128) void batch_pool_kernel(
    const float* __restrict__ x, const int* __restrict__ nidx, const int* __restrict__ batch,
    float* __restrict__ pooled, int relu)
{
    __shared__ float sacc[BBB * HIDD];  // 16 KB
    const int t = threadIdx.x;          // column index
    for (int i = t; i < BBB * HIDD; i += 128) sacc[i] = 0.f;
    __syncthreads();
    for (int m = blockIdx.x; m < MM; m += gridDim.x) {
        int n = __ldg(nidx + m);
        int b = __ldg(batch + m);
        float v = __ldg(x + (size_t)n * HIDD + t);
        if (relu) v = fmaxf(v, 0.f);
        sacc[b * HIDD + t] += v;  // only thread t touches column t -> no race
    }
    __syncthreads();
    for (int i = t; i < BBB * HIDD; i += 128) atomicAdd(pooled + i, sacc[i]);
}

// ---------------- final score: out[b,c] = sum_i pooled[i,b,:] @ Wp[i,:,c] + bp[i,c] --------
__global__ void score_kernel(const float* __restrict__ pooled, const float* __restrict__ Wp,
                             const float* __restrict__ bp, float* __restrict__ out)
{
    int t = threadIdx.x;
    if (t >= BBB * CCC) return;
    int b = t / CCC, c = t % CCC;
    float s = 0.f;
    for (int i = 0; i < 3; i++) {
        const float* p = pooled + (size_t)i * BBB * HIDD + (size_t)b * HIDD;
        const float* w = Wp + (size_t)i * HIDD * CCC;
        float acc = 0.f;
#pragma unroll 4
        for (int k = 0; k < HIDD; k++) acc = fmaf(p[k], w[k * CCC + c], acc);
        s += acc + __ldg(bp + i * CCC + c);
    }
    out[b * CCC + c] = s;
}

// ---------------- host orchestration ----------------
static void zero_buf(float* p, size_t nfloats) {
    size_t n4 = nfloats / 4;
    int grid = (int)((n4 + 255) / 256);
    if (grid > 2048) grid = 2048;
    zero_kernel<<<grid, 256>>>((float4*)p, n4);
}

static void run_gin(const float* Wg, const float* bg, const float* eps_g,
                    const float* gamma, const float* beta,
                    int layer, int dir, const int* src, const int* dst,
                    float* px, float* pagg, float* ph)
{
    const int gemm_grid = (MM + 63) / 64;
    const int scat_grid = (LL * 32) / 256;
    for (int l = 0; l < 2; l++) {
        int base = (layer * 2 + dir) * 2 + l;  // index over [NL,2,INNER]
        const float* W0 = Wg + (size_t)(base * 2 + 0) * HIDD * HIDD;
        const float* W1 = Wg + (size_t)(base * 2 + 1) * HIDD * HIDD;
        const float* b0 = bg + (size_t)(base * 2 + 0) * HIDD;
        const float* b1 = bg + (size_t)(base * 2 + 1) * HIDD;
        const float* ep = eps_g + base;
        const float* gm = gamma + (size_t)base * HIDD;
        const float* bt = beta + (size_t)base * HIDD;

        zero_buf(pagg, (size_t)MM * HIDD);
        scatter_add_kernel<<<scat_grid, 256>>>(px, src, dst, pagg, LL);
        // h = relu(((1+eps)x + agg) @ W0 + b0)
        gemm128<true, 1><<<gemm_grid, 128>>>(px, pagg, ep, W0, b0, nullptr, nullptr, ph, MM);
        // x = BN(h @ W1 + b1), relu if l==0
        if (l == 0)
            gemm128<false, 3><<<gemm_grid, 128>>>(ph, nullptr, nullptr, W1, b1, gm, bt, px, MM);
        else
            gemm128<false, 2><<<gemm_grid, 128>>>(ph, nullptr, nullptr, W1, b1, gm, bt, px, MM);
    }
}

extern "C" void kernel_launch(void* const* d_in, const int* in_sizes, int n_in,
                              void* d_out, int out_size)
{
    const float* x_N   = (const float*)d_in[0];
    const float* We    = (const float*)d_in[1];
    const float* be    = (const float*)d_in[2];
    const float* Wg    = (const float*)d_in[3];
    const float* bg    = (const float*)d_in[4];
    const float* eps_g = (const float*)d_in[5];
    const float* gamma = (const float*)d_in[6];
    const float* beta  = (const float*)d_in[7];
    const float* Wp    = (const float*)d_in[8];
    const float* bp    = (const float*)d_in[9];
    const int* ori_node_idx = (const int*)d_in[10];
    const int* node2edge    = (const int*)d_in[11];
    const int* eiN          = (const int*)d_in[12];  // [2, L]
    const int* ori_edge_idx = (const int*)d_in[13];
    const int* edge2node    = (const int*)d_in[14];
    const int* eiE          = (const int*)d_in[15];  // [2, L]
    const int* batch        = (const int*)d_in[16];
    float* out = (float*)d_out;

    float *px, *pagg, *ph, *pnodex, *pedgex, *ppooled;
    cudaGetSymbolAddress((void**)&px,      g_x);
    cudaGetSymbolAddress((void**)&pagg,    g_agg);
    cudaGetSymbolAddress((void**)&ph,      g_h);
    cudaGetSymbolAddress((void**)&pnodex,  g_nodex);
    cudaGetSymbolAddress((void**)&pedgex,  g_edgex);
    cudaGetSymbolAddress((void**)&ppooled, g_pooled);

    const int gather_grid = (MM * 32) / 256;
    const int pool_grid = 2048;

    // score accumulators
    zero_buf(ppooled, 3 * BBB * HIDD);

    // embedding: node_x = x_N @ We + be
    gemm128<false, 0><<<(NN + 63) / 64, 128>>>(x_N, nullptr, nullptr, We, be,
                                               nullptr, nullptr, pnodex, NN);
    // pool xs[0] (no relu)
    batch_pool_kernel<<<pool_grid, 128>>>(pnodex, ori_node_idx, batch, ppooled + 0, 0);

    for (int i = 0; i < 2; i++) {
        // node -> copies (relu applied at read for i>0: node_x was stored pre-relu)
        gather_kernel<<<gather_grid, 256>>>(pnodex, ori_node_idx, px, MM, i > 0 ? 1 : 0);
        // inner GIN on copy graph N-side
        run_gin(Wg, bg, eps_g, gamma, beta, i, 0, eiN, eiN + LL, px, pagg, ph);
        // pool copies -> hyperedges (relu deferred)
        zero_buf(pedgex, (size_t)NE * HIDD);
        scatter_add_kernel<<<gather_grid, 256>>>(px, nullptr, node2edge, pedgex, MM);
        // edges -> copies with relu
        gather_kernel<<<gather_grid, 256>>>(pedgex, ori_edge_idx, px, MM, 1);
        // inner GIN on copy graph E-side
        run_gin(Wg, bg, eps_g, gamma, beta, i, 1, eiE, eiE + LL, px, pagg, ph);
        // pool copies -> nodes (relu deferred)
        zero_buf(pnodex, (size_t)NN * HIDD);
        scatter_add_kernel<<<gather_grid, 256>>>(px, nullptr, edge2node, pnodex, MM);
        // pool xs[i+1] with relu
        batch_pool_kernel<<<pool_grid, 128>>>(pnodex, ori_node_idx, batch,
                                              ppooled + (size_t)(i + 1) * BBB * HIDD, 1);
    }

    // tiny per-layer head GEMMs + sum
    score_kernel<<<1, BBB * CCC>>>(ppooled, Wp, bp, out);
}

// round 5
// speedup vs baseline: 1.2549x; 1.2549x over previous
#include <cuda_runtime.h>
#include <cstdint>
#include <cstddef>

#define NN   50000
#define NE   20000
#define MM   400000
#define LL   800000
#define HIDD 128
#define BBB  32
#define CCC  10

#define LDA 132   // smem row stride (floats) for A tile
#define LDW 136   // smem row stride (floats) for W hi/lo tiles
#define SMEM_BYTES ((128*LDA + 2*128*LDW) * 4)

// ---------------- scratch (static device globals; no allocs) ----------------
__device__ float g_x[(size_t)MM * HIDD];
__device__ float g_agg[(size_t)MM * HIDD];
__device__ float g_h[(size_t)MM * HIDD];
__device__ float g_nodex[(size_t)NN * HIDD];
__device__ float g_edgex[(size_t)NE * HIDD];
__device__ float g_pooled[3 * BBB * HIDD];

// ---------------- utility kernels ----------------
__global__ void zero_kernel(float4* __restrict__ p, size_t n4) {
    size_t i = (size_t)blockIdx.x * blockDim.x + threadIdx.x;
    size_t stride = (size_t)gridDim.x * blockDim.x;
    float4 z = make_float4(0.f, 0.f, 0.f, 0.f);
    for (; i < n4; i += stride) p[i] = z;
}

// dst[m] = (relu?) src[idx[m]]   rows x 128
__global__ void gather_kernel(const float* __restrict__ src, const int* __restrict__ idx,
                              float* __restrict__ dst, int rows, int relu) {
    int gid = blockIdx.x * blockDim.x + threadIdx.x;
    int m = gid >> 5;
    if (m >= rows) return;
    int c = (gid & 31) << 2;
    int s = __ldg(idx + m);
    float4 v = *(const float4*)(src + (size_t)s * HIDD + c);
    if (relu) {
        v.x = fmaxf(v.x, 0.f); v.y = fmaxf(v.y, 0.f);
        v.z = fmaxf(v.z, 0.f); v.w = fmaxf(v.w, 0.f);
    }
    *(float4*)(dst + (size_t)m * HIDD + c) = v;
}

// out[dsti[e]] += x[ srci ? srci[e] : e ]   (vector f32 reduction, 1 red per 16B)
__global__ void scatter_add_kernel(const float* __restrict__ x, const int* __restrict__ srci,
                                   const int* __restrict__ dsti, float* __restrict__ out, int n) {
    int gid = blockIdx.x * blockDim.x + threadIdx.x;
    int e = gid >> 5;
    if (e >= n) return;
    int c = (gid & 31) << 2;
    int s = srci ? __ldg(srci + e) : e;
    int d = __ldg(dsti + e);
    float4 v = *(const float4*)(x + (size_t)s * HIDD + c);
    float* o = out + (size_t)d * HIDD + c;
    asm volatile("red.global.add.v4.f32 [%0], {%1,%2,%3,%4};"
                 :: "l"(o), "f"(v.x), "f"(v.y), "f"(v.z), "f"(v.w) : "memory");
}

// ---------------- split-TF32 tensor-core GEMM ----------------
__device__ __forceinline__ uint32_t f2tf32(float x) {
    uint32_t r;
    asm("cvt.rna.tf32.f32 %0, %1;" : "=r"(r) : "f"(x));
    return r;
}

__device__ __forceinline__ void mma_tf32(float c[4],
                                         uint32_t a0, uint32_t a1, uint32_t a2, uint32_t a3,
                                         uint32_t b0, uint32_t b1) {
    asm volatile("mma.sync.aligned.m16n8k8.row.col.f32.tf32.tf32.f32 "
                 "{%0,%1,%2,%3}, {%4,%5,%6,%7}, {%8,%9}, {%0,%1,%2,%3};"
                 : "+f"(c[0]), "+f"(c[1]), "+f"(c[2]), "+f"(c[3])
                 : "r"(a0), "r"(a1), "r"(a2), "r"(a3), "r"(b0), "r"(b1));
}

// C[M,128] = pro(A) @ W[128,128] + epilogue.  BM=128, full N=K=128 per block.
// EPI: 0 = +bias ; 1 = relu(+bias) ; 2 = BN(+bias) ; 3 = relu(BN(+bias))
template <bool FUSE, int EPI>
__global__ __launch_bounds__(256, 1) void gemm_tf32(
    const float* __restrict__ A, const float* __restrict__ G, const float* __restrict__ epsp,
    const float* __restrict__ W, const float* __restrict__ bias,
    const float* __restrict__ gamma, const float* __restrict__ beta,
    float* __restrict__ Cmat, int Mrows)
{
    extern __shared__ float smem[];
    float* sA  = smem;                 // [128][LDA]
    float* sWh = smem + 128 * LDA;     // [128][LDW]
    float* sWl = sWh + 128 * LDW;      // [128][LDW]

    const int t = threadIdx.x;
    const int bm0 = blockIdx.x * 128;
    const int lane = t & 31;
    const int wid = t >> 5;
    const int wm = wid & 3;            // 4 warps along M (32 rows each)
    const int wn = wid >> 2;           // 2 warps along N (64 cols each)
    const int m_base = wm * 32;
    const int n_base = wn * 64;
    const int g = lane >> 2;           // groupID 0..7
    const int tg = lane & 3;           // thread in group 0..3

    float e1 = 1.0f;
    if (FUSE) e1 = 1.0f + __ldg(epsp);

    // ---- stage A (with fused prologue) ----
#pragma unroll
    for (int i = 0; i < 16; i++) {
        int qi = t + i * 256;          // 4096 float4s
        int row = qi >> 5;
        int c4 = (qi & 31) * 4;
        int gr = bm0 + row;
        float4 v = make_float4(0.f, 0.f, 0.f, 0.f);
        if (gr < Mrows) {
            size_t off = (size_t)gr * HIDD + c4;
            v = *(const float4*)(A + off);
            if (FUSE) {
                float4 gg = *(const float4*)(G + off);
                v.x = fmaf(e1, v.x, gg.x);
                v.y = fmaf(e1, v.y, gg.y);
                v.z = fmaf(e1, v.z, gg.z);
                v.w = fmaf(e1, v.w, gg.w);
            }
        }
        *(float4*)(sA + row * LDA + c4) = v;
    }
    // ---- stage W split hi/lo ----
#pragma unroll
    for (int i = 0; i < 16; i++) {
        int qi = t + i * 256;
        int row = qi >> 5;
        int c4 = (qi & 31) * 4;
        float4 w = *(const float4*)(W + (size_t)row * HIDD + c4);
        float4 wh, wl;
        uint32_t h;
        h = f2tf32(w.x); wh.x = __uint_as_float(h); wl.x = __uint_as_float(f2tf32(w.x - __uint_as_float(h)));
        h = f2tf32(w.y); wh.y = __uint_as_float(h); wl.y = __uint_as_float(f2tf32(w.y - __uint_as_float(h)));
        h = f2tf32(w.z); wh.z = __uint_as_float(h); wl.z = __uint_as_float(f2tf32(w.z - __uint_as_float(h)));
        h = f2tf32(w.w); wh.w = __uint_as_float(h); wl.w = __uint_as_float(f2tf32(w.w - __uint_as_float(h)));
        *(float4*)(sWh + row * LDW + c4) = wh;
        *(float4*)(sWl + row * LDW + c4) = wl;
    }
    __syncthreads();

    float acc[2][8][4];
#pragma unroll
    for (int mt = 0; mt < 2; mt++)
#pragma unroll
        for (int nt = 0; nt < 8; nt++)
#pragma unroll
            for (int j = 0; j < 4; j++) acc[mt][nt][j] = 0.f;

#pragma unroll 2
    for (int ks = 0; ks < 16; ks++) {
        int k0 = ks * 8;
        uint32_t ah[2][4], al[2][4];
#pragma unroll
        for (int mt = 0; mt < 2; mt++) {
            const float* pa = sA + (m_base + mt * 16 + g) * LDA + k0 + tg;
            float x0 = pa[0];
            float x1 = pa[8 * LDA];
            float x2 = pa[4];
            float x3 = pa[8 * LDA + 4];
            ah[mt][0] = f2tf32(x0); al[mt][0] = f2tf32(x0 - __uint_as_float(ah[mt][0]));
            ah[mt][1] = f2tf32(x1); al[mt][1] = f2tf32(x1 - __uint_as_float(ah[mt][1]));
            ah[mt][2] = f2tf32(x2); al[mt][2] = f2tf32(x2 - __uint_as_float(ah[mt][2]));
            ah[mt][3] = f2tf32(x3); al[mt][3] = f2tf32(x3 - __uint_as_float(ah[mt][3]));
        }
#pragma unroll
        for (int nt = 0; nt < 8; nt++) {
            int col = n_base + nt * 8 + g;
            const float* pwh = sWh + (k0 + tg) * LDW + col;
            const float* pwl = sWl + (k0 + tg) * LDW + col;
            uint32_t bh0 = __float_as_uint(pwh[0]);
            uint32_t bh1 = __float_as_uint(pwh[4 * LDW]);
            uint32_t bl0 = __float_as_uint(pwl[0]);
            uint32_t bl1 = __float_as_uint(pwl[4 * LDW]);
#pragma unroll
            for (int mt = 0; mt < 2; mt++) {
                mma_tf32(acc[mt][nt], ah[mt][0], ah[mt][1], ah[mt][2], ah[mt][3], bh0, bh1);
                mma_tf32(acc[mt][nt], ah[mt][0], ah[mt][1], ah[mt][2], ah[mt][3], bl0, bl1);
                mma_tf32(acc[mt][nt], al[mt][0], al[mt][1], al[mt][2], al[mt][3], bh0, bh1);
            }
        }
    }

    // ---- epilogue ----
    const float inv_std = rsqrtf(1.0f + 1e-5f);
#pragma unroll
    for (int mt = 0; mt < 2; mt++) {
#pragma unroll
        for (int half = 0; half < 2; half++) {
            int row = bm0 + m_base + mt * 16 + g + half * 8;
            if (row >= Mrows) continue;
#pragma unroll
            for (int nt = 0; nt < 8; nt++) {
                int col = n_base + nt * 8 + tg * 2;
                float v0 = acc[mt][nt][half * 2 + 0] + __ldg(bias + col);
                float v1 = acc[mt][nt][half * 2 + 1] + __ldg(bias + col + 1);
                if (EPI == 1) { v0 = fmaxf(v0, 0.f); v1 = fmaxf(v1, 0.f); }
                if (EPI >= 2) {
                    v0 = __ldg(gamma + col) * v0 * inv_std + __ldg(beta + col);
                    v1 = __ldg(gamma + col + 1) * v1 * inv_std + __ldg(beta + col + 1);
                    if (EPI == 3) { v0 = fmaxf(v0, 0.f); v1 = fmaxf(v1, 0.f); }
                }
                *(float2*)(Cmat + (size_t)row * HIDD + col) = make_float2(v0, v1);
            }
        }
    }
}

// ---------------- per-graph pooling ----------------
__global__ __launch_bounds__(128) void batch_pool_kernel(
    const float* __restrict__ x, const int* __restrict__ nidx, const int* __restrict__ batch,
    float* __restrict__ pooled, int relu)
{
    __shared__ float sacc[BBB * HIDD];  // 16 KB
    const int t = threadIdx.x;          // column index
    for (int i = t; i < BBB * HIDD; i += 128) sacc[i] = 0.f;
    __syncthreads();
    for (int m = blockIdx.x; m < MM; m += gridDim.x) {
        int n = __ldg(nidx + m);
        int b = __ldg(batch + m);
        float v = __ldg(x + (size_t)n * HIDD + t);
        if (relu) v = fmaxf(v, 0.f);
        sacc[b * HIDD + t] += v;
    }
    __syncthreads();
    for (int i = t; i < BBB * HIDD; i += 128) atomicAdd(pooled + i, sacc[i]);
}

// ---------------- final score ----------------
__global__ void score_kernel(const float* __restrict__ pooled, const float* __restrict__ Wp,
                             const float* __restrict__ bp, float* __restrict__ out)
{
    int t = threadIdx.x;
    if (t >= BBB * CCC) return;
    int b = t / CCC, c = t % CCC;
    float s = 0.f;
    for (int i = 0; i < 3; i++) {
        const float* p = pooled + (size_t)i * BBB * HIDD + (size_t)b * HIDD;
        const float* w = Wp + (size_t)i * HIDD * CCC;
        float acc = 0.f;
#pragma unroll 4
        for (int k = 0; k < HIDD; k++) acc = fmaf(p[k], w[k * CCC + c], acc);
        s += acc + __ldg(bp + i * CCC + c);
    }
    out[b * CCC + c] = s;
}

// ---------------- host orchestration ----------------
static void zero_buf(float* p, size_t nfloats) {
    size_t n4 = nfloats / 4;
    int grid = (int)((n4 + 255) / 256);
    if (grid > 2048) grid = 2048;
    zero_kernel<<<grid, 256>>>((float4*)p, n4);
}

static void run_gin(const float* Wg, const float* bg, const float* eps_g,
                    const float* gamma, const float* beta,
                    int layer, int dir, const int* src, const int* dst,
                    float* px, float* pagg, float* ph)
{
    const int gemm_grid = (MM + 127) / 128;
    const int scat_grid = (LL * 32) / 256;
    for (int l = 0; l < 2; l++) {
        int base = (layer * 2 + dir) * 2 + l;
        const float* W0 = Wg + (size_t)(base * 2 + 0) * HIDD * HIDD;
        const float* W1 = Wg + (size_t)(base * 2 + 1) * HIDD * HIDD;
        const float* b0 = bg + (size_t)(base * 2 + 0) * HIDD;
        const float* b1 = bg + (size_t)(base * 2 + 1) * HIDD;
        const float* ep = eps_g + base;
        const float* gm = gamma + (size_t)base * HIDD;
        const float* bt = beta + (size_t)base * HIDD;

        zero_buf(pagg, (size_t)MM * HIDD);
        scatter_add_kernel<<<scat_grid, 256>>>(px, src, dst, pagg, LL);
        // h = relu(((1+eps)x + agg) @ W0 + b0)
        gemm_tf32<true, 1><<<gemm_grid, 256, SMEM_BYTES>>>(px, pagg, ep, W0, b0,
                                                           nullptr, nullptr, ph, MM);
        // x = BN(h @ W1 + b1), relu if l==0
        if (l == 0)
            gemm_tf32<false, 3><<<gemm_grid, 256, SMEM_BYTES>>>(ph, nullptr, nullptr, W1, b1,
                                                                gm, bt, px, MM);
        else
            gemm_tf32<false, 2><<<gemm_grid, 256, SMEM_BYTES>>>(ph, nullptr, nullptr, W1, b1,
                                                                gm, bt, px, MM);
    }
}

extern "C" void kernel_launch(void* const* d_in, const int* in_sizes, int n_in,
                              void* d_out, int out_size)
{
    const float* x_N   = (const float*)d_in[0];
    const float* We    = (const float*)d_in[1];
    const float* be    = (const float*)d_in[2];
    const float* Wg    = (const float*)d_in[3];
    const float* bg    = (const float*)d_in[4];
    const float* eps_g = (const float*)d_in[5];
    const float* gamma = (const float*)d_in[6];
    const float* beta  = (const float*)d_in[7];
    const float* Wp    = (const float*)d_in[8];
    const float* bp    = (const float*)d_in[9];
    const int* ori_node_idx = (const int*)d_in[10];
    const int* node2edge    = (const int*)d_in[11];
    const int* eiN          = (const int*)d_in[12];  // [2, L]
    const int* ori_edge_idx = (const int*)d_in[13];
    const int* edge2node    = (const int*)d_in[14];
    const int* eiE          = (const int*)d_in[15];  // [2, L]
    const int* batch        = (const int*)d_in[16];
    float* out = (float*)d_out;

    cudaFuncSetAttribute(gemm_tf32<true, 1>,  cudaFuncAttributeMaxDynamicSharedMemorySize, SMEM_BYTES);
    cudaFuncSetAttribute(gemm_tf32<false, 0>, cudaFuncAttributeMaxDynamicSharedMemorySize, SMEM_BYTES);
    cudaFuncSetAttribute(gemm_tf32<false, 2>, cudaFuncAttributeMaxDynamicSharedMemorySize, SMEM_BYTES);
    cudaFuncSetAttribute(gemm_tf32<false, 3>, cudaFuncAttributeMaxDynamicSharedMemorySize, SMEM_BYTES);

    float *px, *pagg, *ph, *pnodex, *pedgex, *ppooled;
    cudaGetSymbolAddress((void**)&px,      g_x);
    cudaGetSymbolAddress((void**)&pagg,    g_agg);
    cudaGetSymbolAddress((void**)&ph,      g_h);
    cudaGetSymbolAddress((void**)&pnodex,  g_nodex);
    cudaGetSymbolAddress((void**)&pedgex,  g_edgex);
    cudaGetSymbolAddress((void**)&ppooled, g_pooled);

    const int gather_grid = (MM * 32) / 256;
    const int pool_grid = 2048;

    zero_buf(ppooled, 3 * BBB * HIDD);

    // embedding: node_x = x_N @ We + be
    gemm_tf32<false, 0><<<(NN + 127) / 128, 256, SMEM_BYTES>>>(x_N, nullptr, nullptr, We, be,
                                                               nullptr, nullptr, pnodex, NN);
    batch_pool_kernel<<<pool_grid, 128>>>(pnodex, ori_node_idx, batch, ppooled + 0, 0);

    for (int i = 0; i < 2; i++) {
        gather_kernel<<<gather_grid, 256>>>(pnodex, ori_node_idx, px, MM, i > 0 ? 1 : 0);
        run_gin(Wg, bg, eps_g, gamma, beta, i, 0, eiN, eiN + LL, px, pagg, ph);
        zero_buf(pedgex, (size_t)NE * HIDD);
        scatter_add_kernel<<<gather_grid, 256>>>(px, nullptr, node2edge, pedgex, MM);
        gather_kernel<<<gather_grid, 256>>>(pedgex, ori_edge_idx, px, MM, 1);
        run_gin(Wg, bg, eps_g, gamma, beta, i, 1, eiE, eiE + LL, px, pagg, ph);
        zero_buf(pnodex, (size_t)NN * HIDD);
        scatter_add_kernel<<<gather_grid, 256>>>(px, nullptr, edge2node, pnodex, MM);
        batch_pool_kernel<<<pool_grid, 128>>>(pnodex, ori_node_idx, batch,
                                              ppooled + (size_t)(i + 1) * BBB * HIDD, 1);
    }

    score_kernel<<<1, BBB * CCC>>>(ppooled, Wp, bp, out);
}

// round 6
// speedup vs baseline: 1.4632x; 1.1659x over previous
#include <cuda_runtime.h>
#include <cuda_bf16.h>
#include <cstdint>
#include <cstddef>

#define NN   50000
#define NE   20000
#define MM   400000
#define LL   800000
#define HIDD 128
#define BBB  32
#define CCC  10

#define LDK   136          // bf16 elems per smem row (k stride); 68 u32 -> (4g+tg) bank-perfect
#define LDK32 (LDK / 2)
#define SMEM_BYTES (4 * 128 * LDK * 2)   // sAh,sAl,sWh,sWl = 139264 B

// ---------------- scratch (static device globals; no allocs) ----------------
__device__ float g_x[(size_t)MM * HIDD];
__device__ float g_agg[(size_t)MM * HIDD];
__device__ float g_h[(size_t)MM * HIDD];
__device__ float g_nodex[(size_t)NN * HIDD];
__device__ float g_edgex[(size_t)NE * HIDD];
__device__ float g_pooled[3 * BBB * HIDD];

// ---------------- utility kernels ----------------
__global__ void zero_kernel(float4* __restrict__ p, size_t n4) {
    size_t i = (size_t)blockIdx.x * blockDim.x + threadIdx.x;
    size_t stride = (size_t)gridDim.x * blockDim.x;
    float4 z = make_float4(0.f, 0.f, 0.f, 0.f);
    for (; i < n4; i += stride) p[i] = z;
}

// dst[m] = (relu?) src[idx[m]]   rows x 128
__global__ void gather_kernel(const float* __restrict__ src, const int* __restrict__ idx,
                              float* __restrict__ dst, int rows, int relu) {
    int gid = blockIdx.x * blockDim.x + threadIdx.x;
    int m = gid >> 5;
    if (m >= rows) return;
    int c = (gid & 31) << 2;
    int s = __ldg(idx + m);
    float4 v = *(const float4*)(src + (size_t)s * HIDD + c);
    if (relu) {
        v.x = fmaxf(v.x, 0.f); v.y = fmaxf(v.y, 0.f);
        v.z = fmaxf(v.z, 0.f); v.w = fmaxf(v.w, 0.f);
    }
    *(float4*)(dst + (size_t)m * HIDD + c) = v;
}

// out[dsti[e]] += x[ srci ? srci[e] : e ]   (vector f32 reduction)
__global__ void scatter_add_kernel(const float* __restrict__ x, const int* __restrict__ srci,
                                   const int* __restrict__ dsti, float* __restrict__ out, int n) {
    int gid = blockIdx.x * blockDim.x + threadIdx.x;
    int e = gid >> 5;
    if (e >= n) return;
    int c = (gid & 31) << 2;
    int s = srci ? __ldg(srci + e) : e;
    int d = __ldg(dsti + e);
    float4 v = *(const float4*)(x + (size_t)s * HIDD + c);
    float* o = out + (size_t)d * HIDD + c;
    asm volatile("red.global.add.v4.f32 [%0], {%1,%2,%3,%4};"
                 :: "l"(o), "f"(v.x), "f"(v.y), "f"(v.z), "f"(v.w) : "memory");
}

// ---------------- bf16 4-term split tensor-core GEMM ----------------
__device__ __forceinline__ void mma_bf16(float c[4],
                                         uint32_t a0, uint32_t a1, uint32_t a2, uint32_t a3,
                                         uint32_t b0, uint32_t b1) {
    asm volatile("mma.sync.aligned.m16n8k16.row.col.f32.bf16.bf16.f32 "
                 "{%0,%1,%2,%3}, {%4,%5,%6,%7}, {%8,%9}, {%0,%1,%2,%3};"
                 : "+f"(c[0]), "+f"(c[1]), "+f"(c[2]), "+f"(c[3])
                 : "r"(a0), "r"(a1), "r"(a2), "r"(a3), "r"(b0), "r"(b1));
}

__device__ __forceinline__ void split2(float x, float y, uint32_t& h, uint32_t& l) {
    __nv_bfloat162 hp = __floats2bfloat162_rn(x, y);
    float hx = __bfloat162float(hp.x), hy = __bfloat162float(hp.y);
    __nv_bfloat162 lp = __floats2bfloat162_rn(x - hx, y - hy);
    h = *(uint32_t*)&hp;
    l = *(uint32_t*)&lp;
}

// C[M,128] = pro(A) @ W[128,128] + epilogue.  BM=128, full N=K=128 per block.
// EPI: 0 = +bias ; 1 = relu(+bias) ; 2 = BN(+bias) ; 3 = relu(BN(+bias))
template <bool FUSE, int EPI>
__global__ __launch_bounds__(512, 1) void gemm_bf16x4(
    const float* __restrict__ A, const float* __restrict__ G, const float* __restrict__ epsp,
    const float* __restrict__ W, const float* __restrict__ bias,
    const float* __restrict__ gamma, const float* __restrict__ beta,
    float* __restrict__ Cmat, int Mrows)
{
    extern __shared__ __nv_bfloat16 sm[];
    __nv_bfloat16* sAh = sm;
    __nv_bfloat16* sAl = sAh + 128 * LDK;
    __nv_bfloat16* sWh = sAl + 128 * LDK;
    __nv_bfloat16* sWl = sWh + 128 * LDK;

    const int t = threadIdx.x;
    const int bm0 = blockIdx.x * 128;
    const int lane = t & 31;
    const int wid = t >> 5;        // 16 warps
    const int wm = wid & 7;        // 8 warps along M (16 rows each)
    const int wn = wid >> 3;       // 2 warps along N (64 cols each)
    const int m_base = wm * 16;
    const int n_base = wn * 64;
    const int g = lane >> 2;       // groupID 0..7
    const int tg = lane & 3;       // thread-in-group 0..3

    float e1 = 1.0f;
    if (FUSE) e1 = 1.0f + __ldg(epsp);

    // ---- stage A split hi/lo (fused prologue); warp w stages rows w, w+16, ... ----
    uint32_t* Ah32 = (uint32_t*)sAh;
    uint32_t* Al32 = (uint32_t*)sAl;
#pragma unroll
    for (int i = 0; i < 8; i++) {
        int row = wid + i * 16;
        int gr = bm0 + row;
        float4 v = make_float4(0.f, 0.f, 0.f, 0.f);
        if (gr < Mrows) {
            size_t off = (size_t)gr * HIDD + lane * 4;
            v = *(const float4*)(A + off);
            if (FUSE) {
                float4 gg = *(const float4*)(G + off);
                v.x = fmaf(e1, v.x, gg.x);
                v.y = fmaf(e1, v.y, gg.y);
                v.z = fmaf(e1, v.z, gg.z);
                v.w = fmaf(e1, v.w, gg.w);
            }
        }
        uint32_t h01, l01, h23, l23;
        split2(v.x, v.y, h01, l01);
        split2(v.z, v.w, h23, l23);
        Ah32[row * LDK32 + lane * 2 + 0] = h01;
        Ah32[row * LDK32 + lane * 2 + 1] = h23;
        Al32[row * LDK32 + lane * 2 + 0] = l01;
        Al32[row * LDK32 + lane * 2 + 1] = l23;
    }
    // ---- stage W transposed [n][k] split hi/lo ----
#pragma unroll
    for (int i = 0; i < 32; i++) {
        int qi = t + i * 512;          // 16384 elements
        int k = qi >> 7, n = qi & 127; // coalesced global read along n
        float w = __ldg(W + (size_t)k * HIDD + n);
        __nv_bfloat16 h = __float2bfloat16_rn(w);
        __nv_bfloat16 l = __float2bfloat16_rn(w - __bfloat162float(h));
        sWh[n * LDK + k] = h;
        sWl[n * LDK + k] = l;
    }
    __syncthreads();

    float acc[8][4];
#pragma unroll
    for (int nt = 0; nt < 8; nt++)
#pragma unroll
        for (int j = 0; j < 4; j++) acc[nt][j] = 0.f;

    const uint32_t* Wh32 = (const uint32_t*)sWh;
    const uint32_t* Wl32 = (const uint32_t*)sWl;
    const int ra0 = (m_base + g) * LDK32;
    const int ra1 = (m_base + g + 8) * LDK32;

#pragma unroll
    for (int ks = 0; ks < 8; ks++) {
        const int kw = ks * 8 + tg;    // u32 index of k-pair (k = ks*16 + 2*tg)
        uint32_t ah0 = Ah32[ra0 + kw],     ah1 = Ah32[ra1 + kw];
        uint32_t ah2 = Ah32[ra0 + kw + 4], ah3 = Ah32[ra1 + kw + 4];
        uint32_t al0 = Al32[ra0 + kw],     al1 = Al32[ra1 + kw];
        uint32_t al2 = Al32[ra0 + kw + 4], al3 = Al32[ra1 + kw + 4];
#pragma unroll
        for (int nt = 0; nt < 8; nt++) {
            const int rb = (n_base + nt * 8 + g) * LDK32;
            uint32_t bh0 = Wh32[rb + kw], bh1 = Wh32[rb + kw + 4];
            uint32_t bl0 = Wl32[rb + kw], bl1 = Wl32[rb + kw + 4];
            mma_bf16(acc[nt], ah0, ah1, ah2, ah3, bh0, bh1);
            mma_bf16(acc[nt], ah0, ah1, ah2, ah3, bl0, bl1);
            mma_bf16(acc[nt], al0, al1, al2, al3, bh0, bh1);
            mma_bf16(acc[nt], al0, al1, al2, al3, bl0, bl1);
        }
    }

    // ---- epilogue ----
    const float inv_std = rsqrtf(1.0f + 1e-5f);
#pragma unroll
    for (int half = 0; half < 2; half++) {
        int row = bm0 + m_base + g + half * 8;
        if (row >= Mrows) continue;
#pragma unroll
        for (int nt = 0; nt < 8; nt++) {
            int col = n_base + nt * 8 + tg * 2;
            float v0 = acc[nt][half * 2 + 0] + __ldg(bias + col);
            float v1 = acc[nt][half * 2 + 1] + __ldg(bias + col + 1);
            if (EPI == 1) { v0 = fmaxf(v0, 0.f); v1 = fmaxf(v1, 0.f); }
            if (EPI >= 2) {
                v0 = __ldg(gamma + col) * v0 * inv_std + __ldg(beta + col);
                v1 = __ldg(gamma + col + 1) * v1 * inv_std + __ldg(beta + col + 1);
                if (EPI == 3) { v0 = fmaxf(v0, 0.f); v1 = fmaxf(v1, 0.f); }
            }
            *(float2*)(Cmat + (size_t)row * HIDD + col) = make_float2(v0, v1);
        }
    }
}

// ---------------- per-graph pooling ----------------
__global__ __launch_bounds__(128) void batch_pool_kernel(
    const float* __restrict__ x, const int* __restrict__ nidx, const int* __restrict__ batch,
    float* __restrict__ pooled, int relu)
{
    __shared__ float sacc[BBB * HIDD];  // 16 KB
    const int t = threadIdx.x;          // column index
    for (int i = t; i < BBB * HIDD; i += 128) sacc[i] = 0.f;
    __syncthreads();
    for (int m = blockIdx.x; m < MM; m += gridDim.x) {
        int n = __ldg(nidx + m);
        int b = __ldg(batch + m);
        float v = __ldg(x + (size_t)n * HIDD + t);
        if (relu) v = fmaxf(v, 0.f);
        sacc[b * HIDD + t] += v;
    }
    __syncthreads();
    for (int i = t; i < BBB * HIDD; i += 128) atomicAdd(pooled + i, sacc[i]);
}

// ---------------- final score ----------------
__global__ void score_kernel(const float* __restrict__ pooled, const float* __restrict__ Wp,
                             const float* __restrict__ bp, float* __restrict__ out)
{
    int t = threadIdx.x;
    if (t >= BBB * CCC) return;
    int b = t / CCC, c = t % CCC;
    float s = 0.f;
    for (int i = 0; i < 3; i++) {
        const float* p = pooled + (size_t)i * BBB * HIDD + (size_t)b * HIDD;
        const float* w = Wp + (size_t)i * HIDD * CCC;
        float acc = 0.f;
#pragma unroll 4
        for (int k = 0; k < HIDD; k++) acc = fmaf(p[k], w[k * CCC + c], acc);
        s += acc + __ldg(bp + i * CCC + c);
    }
    out[b * CCC + c] = s;
}

// ---------------- host orchestration ----------------
static void zero_buf(float* p, size_t nfloats) {
    size_t n4 = nfloats / 4;
    int grid = (int)((n4 + 255) / 256);
    if (grid > 2048) grid = 2048;
    zero_kernel<<<grid, 256>>>((float4*)p, n4);
}

static void run_gin(const float* Wg, const float* bg, const float* eps_g,
                    const float* gamma, const float* beta,
                    int layer, int dir, const int* src, const int* dst,
                    float* px, float* pagg, float* ph)
{
    const int gemm_grid = (MM + 127) / 128;
    const int scat_grid = (LL * 32) / 256;
    for (int l = 0; l < 2; l++) {
        int base = (layer * 2 + dir) * 2 + l;
        const float* W0 = Wg + (size_t)(base * 2 + 0) * HIDD * HIDD;
        const float* W1 = Wg + (size_t)(base * 2 + 1) * HIDD * HIDD;
        const float* b0 = bg + (size_t)(base * 2 + 0) * HIDD;
        const float* b1 = bg + (size_t)(base * 2 + 1) * HIDD;
        const float* ep = eps_g + base;
        const float* gm = gamma + (size_t)base * HIDD;
        const float* bt = beta + (size_t)base * HIDD;

        zero_buf(pagg, (size_t)MM * HIDD);
        scatter_add_kernel<<<scat_grid, 256>>>(px, src, dst, pagg, LL);
        // h = relu(((1+eps)x + agg) @ W0 + b0)
        gemm_bf16x4<true, 1><<<gemm_grid, 512, SMEM_BYTES>>>(px, pagg, ep, W0, b0,
                                                             nullptr, nullptr, ph, MM);
        // x = BN(h @ W1 + b1), relu if l==0
        if (l == 0)
            gemm_bf16x4<false, 3><<<gemm_grid, 512, SMEM_BYTES>>>(ph, nullptr, nullptr, W1, b1,
                                                                  gm, bt, px, MM);
        else
            gemm_bf16x4<false, 2><<<gemm_grid, 512, SMEM_BYTES>>>(ph, nullptr, nullptr, W1, b1,
                                                                  gm, bt, px, MM);
    }
}

extern "C" void kernel_launch(void* const* d_in, const int* in_sizes, int n_in,
                              void* d_out, int out_size)
{
    const float* x_N   = (const float*)d_in[0];
    const float* We    = (const float*)d_in[1];
    const float* be    = (const float*)d_in[2];
    const float* Wg    = (const float*)d_in[3];
    const float* bg    = (const float*)d_in[4];
    const float* eps_g = (const float*)d_in[5];
    const float* gamma = (const float*)d_in[6];
    const float* beta  = (const float*)d_in[7];
    const float* Wp    = (const float*)d_in[8];
    const float* bp    = (const float*)d_in[9];
    const int* ori_node_idx = (const int*)d_in[10];
    const int* node2edge    = (const int*)d_in[11];
    const int* eiN          = (const int*)d_in[12];  // [2, L]
    const int* ori_edge_idx = (const int*)d_in[13];
    const int* edge2node    = (const int*)d_in[14];
    const int* eiE          = (const int*)d_in[15];  // [2, L]
    const int* batch        = (const int*)d_in[16];
    float* out = (float*)d_out;

    cudaFuncSetAttribute(gemm_bf16x4<true, 1>,  cudaFuncAttributeMaxDynamicSharedMemorySize, SMEM_BYTES);
    cudaFuncSetAttribute(gemm_bf16x4<false, 0>, cudaFuncAttributeMaxDynamicSharedMemorySize, SMEM_BYTES);
    cudaFuncSetAttribute(gemm_bf16x4<false, 2>, cudaFuncAttributeMaxDynamicSharedMemorySize, SMEM_BYTES);
    cudaFuncSetAttribute(gemm_bf16x4<false, 3>, cudaFuncAttributeMaxDynamicSharedMemorySize, SMEM_BYTES);

    float *px, *pagg, *ph, *pnodex, *pedgex, *ppooled;
    cudaGetSymbolAddress((void**)&px,      g_x);
    cudaGetSymbolAddress((void**)&pagg,    g_agg);
    cudaGetSymbolAddress((void**)&ph,      g_h);
    cudaGetSymbolAddress((void**)&pnodex,  g_nodex);
    cudaGetSymbolAddress((void**)&pedgex,  g_edgex);
    cudaGetSymbolAddress((void**)&ppooled, g_pooled);

    const int gather_grid = (MM * 32) / 256;
    const int pool_grid = 2048;

    zero_buf(ppooled, 3 * BBB * HIDD);

    // embedding: node_x = x_N @ We + be
    gemm_bf16x4<false, 0><<<(NN + 127) / 128, 512, SMEM_BYTES>>>(x_N, nullptr, nullptr, We, be,
                                                                 nullptr, nullptr, pnodex, NN);
    batch_pool_kernel<<<pool_grid, 128>>>(pnodex, ori_node_idx, batch, ppooled + 0, 0);

    for (int i = 0; i < 2; i++) {
        gather_kernel<<<gather_grid, 256>>>(pnodex, ori_node_idx, px, MM, i > 0 ? 1 : 0);
        run_gin(Wg, bg, eps_g, gamma, beta, i, 0, eiN, eiN + LL, px, pagg, ph);
        zero_buf(pedgex, (size_t)NE * HIDD);
        scatter_add_kernel<<<gather_grid, 256>>>(px, nullptr, node2edge, pedgex, MM);
        gather_kernel<<<gather_grid, 256>>>(pedgex, ori_edge_idx, px, MM, 1);
        run_gin(Wg, bg, eps_g, gamma, beta, i, 1, eiE, eiE + LL, px, pagg, ph);
        zero_buf(pnodex, (size_t)NN * HIDD);
        scatter_add_kernel<<<gather_grid, 256>>>(px, nullptr, edge2node, pnodex, MM);
        batch_pool_kernel<<<pool_grid, 128>>>(pnodex, ori_node_idx, batch,
                                              ppooled + (size_t)(i + 1) * BBB * HIDD, 1);
    }

    score_kernel<<<1, BBB * CCC>>>(ppooled, Wp, bp, out);
}

// round 7
// speedup vs baseline: 1.5745x; 1.0761x over previous
#include <cuda_runtime.h>
#include <cuda_bf16.h>
#include <cstdint>
#include <cstddef>

#define NN   50000
#define NE   20000
#define MM   400000
#define LL   800000
#define HIDD 128
#define BBB  32
#define CCC  10

#define LDK   136          // bf16 elems per smem row (k stride)
#define LDK32 (LDK / 2)
#define PLANE (128 * LDK)  // bf16 elems per plane
#define SMEM_GIN   (6 * PLANE * 2)   // 208,896 B
#define SMEM_EMBED (4 * PLANE * 2)   // 139,264 B

// ---------------- scratch (static device globals; no allocs) ----------------
__device__ float g_x[(size_t)MM * HIDD];
__device__ float g_agg[(size_t)MM * HIDD];
__device__ float g_nodex[(size_t)NN * HIDD];
__device__ float g_edgex[(size_t)NE * HIDD];
__device__ float g_pooled[3 * BBB * HIDD];

// ---------------- utility kernels ----------------
__global__ void zero_kernel(float4* __restrict__ p, size_t n4) {
    size_t i = (size_t)blockIdx.x * blockDim.x + threadIdx.x;
    size_t stride = (size_t)gridDim.x * blockDim.x;
    float4 z = make_float4(0.f, 0.f, 0.f, 0.f);
    for (; i < n4; i += stride) p[i] = z;
}

// out[dsti[e]] += relu?( x[ rid? rid[s] : s ] ), s = srci?srci[e]:e
__global__ void scatter_add_kernel(const float* __restrict__ x, const int* __restrict__ rid,
                                   int relu, const int* __restrict__ srci,
                                   const int* __restrict__ dsti, float* __restrict__ out, int n) {
    int gid = blockIdx.x * blockDim.x + threadIdx.x;
    int e = gid >> 5;
    if (e >= n) return;
    int c = (gid & 31) << 2;
    int s = srci ? __ldg(srci + e) : e;
    if (rid) s = __ldg(rid + s);
    int d = __ldg(dsti + e);
    float4 v = *(const float4*)(x + (size_t)s * HIDD + c);
    if (relu) {
        v.x = fmaxf(v.x, 0.f); v.y = fmaxf(v.y, 0.f);
        v.z = fmaxf(v.z, 0.f); v.w = fmaxf(v.w, 0.f);
    }
    float* o = out + (size_t)d * HIDD + c;
    asm volatile("red.global.add.v4.f32 [%0], {%1,%2,%3,%4};"
                 :: "l"(o), "f"(v.x), "f"(v.y), "f"(v.z), "f"(v.w) : "memory");
}

// ---------------- bf16 3-term split tensor-core helpers ----------------
__device__ __forceinline__ void mma_bf16(float c[4],
                                         uint32_t a0, uint32_t a1, uint32_t a2, uint32_t a3,
                                         uint32_t b0, uint32_t b1) {
    asm volatile("mma.sync.aligned.m16n8k16.row.col.f32.bf16.bf16.f32 "
                 "{%0,%1,%2,%3}, {%4,%5,%6,%7}, {%8,%9}, {%0,%1,%2,%3};"
                 : "+f"(c[0]), "+f"(c[1]), "+f"(c[2]), "+f"(c[3])
                 : "r"(a0), "r"(a1), "r"(a2), "r"(a3), "r"(b0), "r"(b1));
}

__device__ __forceinline__ void split2(float x, float y, uint32_t& h, uint32_t& l) {
    __nv_bfloat162 hp = __floats2bfloat162_rn(x, y);
    float hx = __bfloat162float(hp.x), hy = __bfloat162float(hp.y);
    __nv_bfloat162 lp = __floats2bfloat162_rn(x - hx, y - hy);
    h = *(uint32_t*)&hp;
    l = *(uint32_t*)&lp;
}

// 3-term split mainloop: acc += A @ B  (A rows ra0/ra1, B cols from n_base)
__device__ __forceinline__ void mainloop3(const uint32_t* __restrict__ Ah,
                                          const uint32_t* __restrict__ Al,
                                          const uint32_t* __restrict__ Bh,
                                          const uint32_t* __restrict__ Bl,
                                          int ra0, int ra1, int n_base, int g, int tg,
                                          float acc[8][4]) {
#pragma unroll
    for (int ks = 0; ks < 8; ks++) {
        const int kw = ks * 8 + tg;
        uint32_t ah0 = Ah[ra0 + kw],     ah1 = Ah[ra1 + kw];
        uint32_t ah2 = Ah[ra0 + kw + 4], ah3 = Ah[ra1 + kw + 4];
        uint32_t al0 = Al[ra0 + kw],     al1 = Al[ra1 + kw];
        uint32_t al2 = Al[ra0 + kw + 4], al3 = Al[ra1 + kw + 4];
#pragma unroll
        for (int nt = 0; nt < 8; nt++) {
            const int rb = (n_base + nt * 8 + g) * LDK32;
            uint32_t bh0 = Bh[rb + kw], bh1 = Bh[rb + kw + 4];
            uint32_t bl0 = Bl[rb + kw], bl1 = Bl[rb + kw + 4];
            mma_bf16(acc[nt], ah0, ah1, ah2, ah3, bh0, bh1);
            mma_bf16(acc[nt], ah0, ah1, ah2, ah3, bl0, bl1);
            mma_bf16(acc[nt], al0, al1, al2, al3, bh0, bh1);
        }
    }
}

// ---------------- fused inner-GIN conv: C = BN(relu(pre@W0+b0)@W1+b1) [+relu] ----------
// pre = (1+eps) * relu?(A[ridx?ridx[row]:row]) + G[row]
// EPI2: 2 = BN ; 3 = relu(BN)
template <int EPI2>
__global__ __launch_bounds__(512, 1) void gin_fused(
    const float* __restrict__ A, const int* __restrict__ ridx, int relu_in,
    const float* __restrict__ G, const float* __restrict__ epsp,
    const float* __restrict__ W0, const float* __restrict__ b0,
    const float* __restrict__ W1, const float* __restrict__ b1,
    const float* __restrict__ gamma, const float* __restrict__ beta,
    float* __restrict__ Cmat, int Mrows)
{
    extern __shared__ __nv_bfloat16 sm[];
    __nv_bfloat16* sAh  = sm;
    __nv_bfloat16* sAl  = sAh + PLANE;
    __nv_bfloat16* sW0h = sAl + PLANE;
    __nv_bfloat16* sW0l = sW0h + PLANE;
    __nv_bfloat16* sW1h = sW0l + PLANE;
    __nv_bfloat16* sW1l = sW1h + PLANE;

    const int t = threadIdx.x;
    const int bm0 = blockIdx.x * 128;
    const int lane = t & 31;
    const int wid = t >> 5;        // 16 warps
    const int wm = wid & 7;        // 8 warps along M (16 rows each)
    const int wn = wid >> 3;       // 2 warps along N (64 cols each)
    const int m_base = wm * 16;
    const int n_base = wn * 64;
    const int g = lane >> 2;
    const int tg = lane & 3;

    const float e1 = 1.0f + __ldg(epsp);

    uint32_t* Ah32 = (uint32_t*)sAh;
    uint32_t* Al32 = (uint32_t*)sAl;

    // ---- stage A (indirect gather + relu + (1+eps)x + agg), split hi/lo ----
#pragma unroll
    for (int i = 0; i < 8; i++) {
        int row = wid + i * 16;
        int gr = bm0 + row;
        float4 v = make_float4(0.f, 0.f, 0.f, 0.f);
        if (gr < Mrows) {
            int sr = ridx ? __ldg(ridx + gr) : gr;
            v = *(const float4*)(A + (size_t)sr * HIDD + lane * 4);
            if (relu_in) {
                v.x = fmaxf(v.x, 0.f); v.y = fmaxf(v.y, 0.f);
                v.z = fmaxf(v.z, 0.f); v.w = fmaxf(v.w, 0.f);
            }
            float4 gg = *(const float4*)(G + (size_t)gr * HIDD + lane * 4);
            v.x = fmaf(e1, v.x, gg.x);
            v.y = fmaf(e1, v.y, gg.y);
            v.z = fmaf(e1, v.z, gg.z);
            v.w = fmaf(e1, v.w, gg.w);
        }
        uint32_t h01, l01, h23, l23;
        split2(v.x, v.y, h01, l01);
        split2(v.z, v.w, h23, l23);
        Ah32[row * LDK32 + lane * 2 + 0] = h01;
        Ah32[row * LDK32 + lane * 2 + 1] = h23;
        Al32[row * LDK32 + lane * 2 + 0] = l01;
        Al32[row * LDK32 + lane * 2 + 1] = l23;
    }
    // ---- stage W0, W1 transposed [n][k], split hi/lo ----
#pragma unroll
    for (int i = 0; i < 32; i++) {
        int qi = t + i * 512;
        int k = qi >> 7, n = qi & 127;
        float w0 = __ldg(W0 + (size_t)k * HIDD + n);
        __nv_bfloat16 h0 = __float2bfloat16_rn(w0);
        sW0h[n * LDK + k] = h0;
        sW0l[n * LDK + k] = __float2bfloat16_rn(w0 - __bfloat162float(h0));
        float w1 = __ldg(W1 + (size_t)k * HIDD + n);
        __nv_bfloat16 h1 = __float2bfloat16_rn(w1);
        sW1h[n * LDK + k] = h1;
        sW1l[n * LDK + k] = __float2bfloat16_rn(w1 - __bfloat162float(h1));
    }
    __syncthreads();

    float acc[8][4];
#pragma unroll
    for (int nt = 0; nt < 8; nt++)
#pragma unroll
        for (int j = 0; j < 4; j++) acc[nt][j] = 0.f;

    const int ra0 = (m_base + g) * LDK32;
    const int ra1 = (m_base + g + 8) * LDK32;

    // ---- GEMM1: pre @ W0 ----
    mainloop3(Ah32, Al32, (const uint32_t*)sW0h, (const uint32_t*)sW0l,
              ra0, ra1, n_base, g, tg, acc);
    __syncthreads();   // all reads of sA done before overwrite

    // ---- epilogue1: h = relu(acc + b0) -> back into sA planes (split) ----
#pragma unroll
    for (int half = 0; half < 2; half++) {
        int rowl = m_base + g + half * 8;
#pragma unroll
        for (int nt = 0; nt < 8; nt++) {
            int col = n_base + nt * 8 + tg * 2;
            float v0 = fmaxf(acc[nt][half * 2 + 0] + __ldg(b0 + col), 0.f);
            float v1 = fmaxf(acc[nt][half * 2 + 1] + __ldg(b0 + col + 1), 0.f);
            uint32_t h, l;
            split2(v0, v1, h, l);
            Ah32[rowl * LDK32 + (col >> 1)] = h;
            Al32[rowl * LDK32 + (col >> 1)] = l;
        }
    }
    __syncthreads();

#pragma unroll
    for (int nt = 0; nt < 8; nt++)
#pragma unroll
        for (int j = 0; j < 4; j++) acc[nt][j] = 0.f;

    // ---- GEMM2: h @ W1 ----
    mainloop3(Ah32, Al32, (const uint32_t*)sW1h, (const uint32_t*)sW1l,
              ra0, ra1, n_base, g, tg, acc);

    // ---- epilogue2: BN(+b1) [+relu] -> global ----
    const float inv_std = rsqrtf(1.0f + 1e-5f);
#pragma unroll
    for (int half = 0; half < 2; half++) {
        int row = bm0 + m_base + g + half * 8;
        if (row >= Mrows) continue;
#pragma unroll
        for (int nt = 0; nt < 8; nt++) {
            int col = n_base + nt * 8 + tg * 2;
            float v0 = acc[nt][half * 2 + 0] + __ldg(b1 + col);
            float v1 = acc[nt][half * 2 + 1] + __ldg(b1 + col + 1);
            v0 = __ldg(gamma + col) * v0 * inv_std + __ldg(beta + col);
            v1 = __ldg(gamma + col + 1) * v1 * inv_std + __ldg(beta + col + 1);
            if (EPI2 == 3) { v0 = fmaxf(v0, 0.f); v1 = fmaxf(v1, 0.f); }
            *(float2*)(Cmat + (size_t)row * HIDD + col) = make_float2(v0, v1);
        }
    }
}

// ---------------- plain GEMM for embedding: C = A @ W + bias ----------------
__global__ __launch_bounds__(512, 1) void gemm_embed(
    const float* __restrict__ A, const float* __restrict__ W, const float* __restrict__ bias,
    float* __restrict__ Cmat, int Mrows)
{
    extern __shared__ __nv_bfloat16 sm[];
    __nv_bfloat16* sAh = sm;
    __nv_bfloat16* sAl = sAh + PLANE;
    __nv_bfloat16* sWh = sAl + PLANE;
    __nv_bfloat16* sWl = sWh + PLANE;

    const int t = threadIdx.x;
    const int bm0 = blockIdx.x * 128;
    const int lane = t & 31;
    const int wid = t >> 5;
    const int wm = wid & 7;
    const int wn = wid >> 3;
    const int m_base = wm * 16;
    const int n_base = wn * 64;
    const int g = lane >> 2;
    const int tg = lane & 3;

    uint32_t* Ah32 = (uint32_t*)sAh;
    uint32_t* Al32 = (uint32_t*)sAl;
#pragma unroll
    for (int i = 0; i < 8; i++) {
        int row = wid + i * 16;
        int gr = bm0 + row;
        float4 v = make_float4(0.f, 0.f, 0.f, 0.f);
        if (gr < Mrows) v = *(const float4*)(A + (size_t)gr * HIDD + lane * 4);
        uint32_t h01, l01, h23, l23;
        split2(v.x, v.y, h01, l01);
        split2(v.z, v.w, h23, l23);
        Ah32[row * LDK32 + lane * 2 + 0] = h01;
        Ah32[row * LDK32 + lane * 2 + 1] = h23;
        Al32[row * LDK32 + lane * 2 + 0] = l01;
        Al32[row * LDK32 + lane * 2 + 1] = l23;
    }
#pragma unroll
    for (int i = 0; i < 32; i++) {
        int qi = t + i * 512;
        int k = qi >> 7, n = qi & 127;
        float w = __ldg(W + (size_t)k * HIDD + n);
        __nv_bfloat16 h = __float2bfloat16_rn(w);
        sWh[n * LDK + k] = h;
        sWl[n * LDK + k] = __float2bfloat16_rn(w - __bfloat162float(h));
    }
    __syncthreads();

    float acc[8][4];
#pragma unroll
    for (int nt = 0; nt < 8; nt++)
#pragma unroll
        for (int j = 0; j < 4; j++) acc[nt][j] = 0.f;

    const int ra0 = (m_base + g) * LDK32;
    const int ra1 = (m_base + g + 8) * LDK32;
    mainloop3(Ah32, Al32, (const uint32_t*)sWh, (const uint32_t*)sWl,
              ra0, ra1, n_base, g, tg, acc);

#pragma unroll
    for (int half = 0; half < 2; half++) {
        int row = bm0 + m_base + g + half * 8;
        if (row >= Mrows) continue;
#pragma unroll
        for (int nt = 0; nt < 8; nt++) {
            int col = n_base + nt * 8 + tg * 2;
            float v0 = acc[nt][half * 2 + 0] + __ldg(bias + col);
            float v1 = acc[nt][half * 2 + 1] + __ldg(bias + col + 1);
            *(float2*)(Cmat + (size_t)row * HIDD + col) = make_float2(v0, v1);
        }
    }
}

// ---------------- per-graph pooling ----------------
__global__ __launch_bounds__(128) void batch_pool_kernel(
    const float* __restrict__ x, const int* __restrict__ nidx, const int* __restrict__ batch,
    float* __restrict__ pooled, int relu)
{
    __shared__ float sacc[BBB * HIDD];
    const int t = threadIdx.x;
    for (int i = t; i < BBB * HIDD; i += 128) sacc[i] = 0.f;
    __syncthreads();
    for (int m = blockIdx.x; m < MM; m += gridDim.x) {
        int n = __ldg(nidx + m);
        int b = __ldg(batch + m);
        float v = __ldg(x + (size_t)n * HIDD + t);
        if (relu) v = fmaxf(v, 0.f);
        sacc[b * HIDD + t] += v;
    }
    __syncthreads();
    for (int i = t; i < BBB * HIDD; i += 128) atomicAdd(pooled + i, sacc[i]);
}

// ---------------- final score ----------------
__global__ void score_kernel(const float* __restrict__ pooled, const float* __restrict__ Wp,
                             const float* __restrict__ bp, float* __restrict__ out)
{
    int t = threadIdx.x;
    if (t >= BBB * CCC) return;
    int b = t / CCC, c = t % CCC;
    float s = 0.f;
    for (int i = 0; i < 3; i++) {
        const float* p = pooled + (size_t)i * BBB * HIDD + (size_t)b * HIDD;
        const float* w = Wp + (size_t)i * HIDD * CCC;
        float acc = 0.f;
#pragma unroll 4
        for (int k = 0; k < HIDD; k++) acc = fmaf(p[k], w[k * CCC + c], acc);
        s += acc + __ldg(bp + i * CCC + c);
    }
    out[b * CCC + c] = s;
}

// ---------------- host orchestration ----------------
static void zero_buf(float* p, size_t nfloats) {
    size_t n4 = nfloats / 4;
    int grid = (int)((n4 + 255) / 256);
    if (grid > 2048) grid = 2048;
    zero_kernel<<<grid, 256>>>((float4*)p, n4);
}

static void run_gin(const float* Wg, const float* bg, const float* eps_g,
                    const float* gamma, const float* beta,
                    int layer, int dir, const int* src, const int* dst,
                    const float* Ain, const int* ridx, int relu_in,
                    float* px, float* pagg)
{
    const int gemm_grid = (MM + 127) / 128;
    const int scat_grid = (LL * 32) / 256;
    for (int l = 0; l < 2; l++) {
        int base = (layer * 2 + dir) * 2 + l;
        const float* W0 = Wg + (size_t)(base * 2 + 0) * HIDD * HIDD;
        const float* W1 = Wg + (size_t)(base * 2 + 1) * HIDD * HIDD;
        const float* b0 = bg + (size_t)(base * 2 + 0) * HIDD;
        const float* b1 = bg + (size_t)(base * 2 + 1) * HIDD;
        const float* ep = eps_g + base;
        const float* gm = gamma + (size_t)base * HIDD;
        const float* bt = beta + (size_t)base * HIDD;

        const float* A   = (l == 0) ? Ain  : px;
        const int*   rix = (l == 0) ? ridx : nullptr;
        int          rl  = (l == 0) ? relu_in : 0;

        zero_buf(pagg, (size_t)MM * HIDD);
        scatter_add_kernel<<<scat_grid, 256>>>(A, rix, rl, src, dst, pagg, LL);
        if (l == 0)
            gin_fused<3><<<gemm_grid, 512, SMEM_GIN>>>(A, rix, rl, pagg, ep,
                                                       W0, b0, W1, b1, gm, bt, px, MM);
        else
            gin_fused<2><<<gemm_grid, 512, SMEM_GIN>>>(A, rix, rl, pagg, ep,
                                                       W0, b0, W1, b1, gm, bt, px, MM);
    }
}

extern "C" void kernel_launch(void* const* d_in, const int* in_sizes, int n_in,
                              void* d_out, int out_size)
{
    const float* x_N   = (const float*)d_in[0];
    const float* We    = (const float*)d_in[1];
    const float* be    = (const float*)d_in[2];
    const float* Wg    = (const float*)d_in[3];
    const float* bg    = (const float*)d_in[4];
    const float* eps_g = (const float*)d_in[5];
    const float* gamma = (const float*)d_in[6];
    const float* beta  = (const float*)d_in[7];
    const float* Wp    = (const float*)d_in[8];
    const float* bp    = (const float*)d_in[9];
    const int* ori_node_idx = (const int*)d_in[10];
    const int* node2edge    = (const int*)d_in[11];
    const int* eiN          = (const int*)d_in[12];  // [2, L]
    const int* ori_edge_idx = (const int*)d_in[13];
    const int* edge2node    = (const int*)d_in[14];
    const int* eiE          = (const int*)d_in[15];  // [2, L]
    const int* batch        = (const int*)d_in[16];
    float* out = (float*)d_out;

    cudaFuncSetAttribute(gin_fused<2>, cudaFuncAttributeMaxDynamicSharedMemorySize, SMEM_GIN);
    cudaFuncSetAttribute(gin_fused<3>, cudaFuncAttributeMaxDynamicSharedMemorySize, SMEM_GIN);
    cudaFuncSetAttribute(gemm_embed,   cudaFuncAttributeMaxDynamicSharedMemorySize, SMEM_EMBED);

    float *px, *pagg, *pnodex, *pedgex, *ppooled;
    cudaGetSymbolAddress((void**)&px,      g_x);
    cudaGetSymbolAddress((void**)&pagg,    g_agg);
    cudaGetSymbolAddress((void**)&pnodex,  g_nodex);
    cudaGetSymbolAddress((void**)&pedgex,  g_edgex);
    cudaGetSymbolAddress((void**)&ppooled, g_pooled);

    const int scat_mm_grid = (MM * 32) / 256;
    const int pool_grid = 2048;

    zero_buf(ppooled, 3 * BBB * HIDD);

    // embedding: node_x = x_N @ We + be
    gemm_embed<<<(NN + 127) / 128, 512, SMEM_EMBED>>>(x_N, We, be, pnodex, NN);
    batch_pool_kernel<<<pool_grid, 128>>>(pnodex, ori_node_idx, batch, ppooled + 0, 0);

    for (int i = 0; i < 2; i++) {
        // N-side GIN over copies (gather folded in; relu deferred for i>0)
        run_gin(Wg, bg, eps_g, gamma, beta, i, 0, eiN, eiN + LL,
                pnodex, ori_node_idx, i > 0 ? 1 : 0, px, pagg);
        // pool copies -> hyperedges (relu deferred to consumers)
        zero_buf(pedgex, (size_t)NE * HIDD);
        scatter_add_kernel<<<scat_mm_grid, 256>>>(px, nullptr, 0, nullptr, node2edge, pedgex, MM);
        // E-side GIN over copies (edge gather + relu folded in)
        run_gin(Wg, bg, eps_g, gamma, beta, i, 1, eiE, eiE + LL,
                pedgex, ori_edge_idx, 1, px, pagg);
        // pool copies -> nodes (relu deferred)
        zero_buf(pnodex, (size_t)NN * HIDD);
        scatter_add_kernel<<<scat_mm_grid, 256>>>(px, nullptr, 0, nullptr, edge2node, pnodex, MM);
        // per-graph pooling of xs[i+1] (with relu)
        batch_pool_kernel<<<pool_grid, 128>>>(pnodex, ori_node_idx, batch,
                                              ppooled + (size_t)(i + 1) * BBB * HIDD, 1);
    }

    score_kernel<<<1, BBB * CCC>>>(ppooled, Wp, bp, out);
}